// round 4
// baseline (speedup 1.0000x reference)
#include <cuda_runtime.h>
#include <cuda_bf16.h>

// CenterLoss: loss = (1/(B*C)) * sum_i ||x_i - centers[labels_i]||^2
// B=4096, C=20000, D=128. Gather + reduce, single launch.
// - 128 blocks x 256 threads, each warp handles 4 rows -> MLP=8 per thread.
// - Last-block-done via atom.acq_rel ticket (NO __threadfence -> no CCTL.IVALL L1 flush).
// - Ticket wraps so state self-resets across graph replays.

#define CL_BATCH 4096
#define CL_FEAT 128
#define CL_NCLASSES 20000
#define CL_ROWS_PER_WARP 4
#define CL_WARPS 8
#define CL_THREADS (CL_WARPS * 32)                       // 256
#define CL_ROWS_PER_BLOCK (CL_ROWS_PER_WARP * CL_WARPS)  // 32
#define CL_NBLOCKS (CL_BATCH / CL_ROWS_PER_BLOCK)        // 128

__device__ float cl_g_partials[CL_NBLOCKS];
__device__ unsigned cl_g_ticket = 0;

__global__ void __launch_bounds__(CL_THREADS) cl_fused_kernel(
    const float* __restrict__ x,
    const int* __restrict__ labels,
    const float* __restrict__ centers,
    float* __restrict__ out)
{
    const int warp = threadIdx.x >> 5;
    const int lane = threadIdx.x & 31;
    const int rowBase = blockIdx.x * CL_ROWS_PER_BLOCK + warp * CL_ROWS_PER_WARP;

    // x loads: independent of labels, issue first (4 outstanding).
    float4 xv[CL_ROWS_PER_WARP];
    #pragma unroll
    for (int r = 0; r < CL_ROWS_PER_WARP; r++)
        xv[r] = reinterpret_cast<const float4*>(x + (size_t)(rowBase + r) * CL_FEAT)[lane];

    // labels: 4 per warp, one tiny load then shuffle (no shared, no barrier).
    int l = 0;
    if (lane < CL_ROWS_PER_WARP) l = labels[rowBase + lane];

    // center gathers (4 more outstanding loads).
    float4 cv[CL_ROWS_PER_WARP];
    #pragma unroll
    for (int r = 0; r < CL_ROWS_PER_WARP; r++) {
        int lab = __shfl_sync(0xffffffffu, l, r);
        cv[r] = reinterpret_cast<const float4*>(centers + (size_t)lab * CL_FEAT)[lane];
    }

    float s = 0.0f;
    #pragma unroll
    for (int r = 0; r < CL_ROWS_PER_WARP; r++) {
        float dx = xv[r].x - cv[r].x;
        float dy = xv[r].y - cv[r].y;
        float dz = xv[r].z - cv[r].z;
        float dw = xv[r].w - cv[r].w;
        s += dx * dx + dy * dy + dz * dz + dw * dw;
    }

    // warp reduction
    #pragma unroll
    for (int o = 16; o > 0; o >>= 1)
        s += __shfl_xor_sync(0xffffffffu, s, o);

    __shared__ float sm[CL_WARPS];
    __shared__ bool s_is_last;
    if (lane == 0) sm[warp] = s;
    __syncthreads();

    if (threadIdx.x == 0) {
        float t = 0.0f;
        #pragma unroll
        for (int i = 0; i < CL_WARPS; i++) t += sm[i];
        cl_g_partials[blockIdx.x] = t;
        // Release-RMW ticket: orders the partial store; acquire side makes all
        // prior partials visible to the last block. No L1-flushing fence.
        unsigned prev;
        asm volatile("atom.acq_rel.gpu.global.inc.u32 %0, [%1], %2;"
                     : "=r"(prev)
                     : "l"(&cl_g_ticket), "r"((unsigned)(CL_NBLOCKS - 1))
                     : "memory");
        s_is_last = (prev == CL_NBLOCKS - 1);
    }
    __syncthreads();

    if (s_is_last) {
        // Deterministic final reduction over 128 partials, read via L2 (.cg).
        float t = 0.0f;
        if (threadIdx.x < CL_NBLOCKS)
            t = __ldcg(&cl_g_partials[threadIdx.x]);

        #pragma unroll
        for (int o = 16; o > 0; o >>= 1)
            t += __shfl_xor_sync(0xffffffffu, t, o);

        __shared__ float sm2[CL_WARPS];
        if (lane == 0) sm2[warp] = t;
        __syncthreads();

        if (threadIdx.x < 32) {
            float u = (threadIdx.x < CL_WARPS) ? sm2[threadIdx.x] : 0.0f;
            #pragma unroll
            for (int o = 4; o > 0; o >>= 1)
                u += __shfl_xor_sync(0xffffffffu, u, o);
            if (threadIdx.x == 0) {
                const float inv = 1.0f / ((float)CL_BATCH * (float)CL_NCLASSES);
                *out = u * inv;
            }
        }
    }
}

extern "C" void kernel_launch(void* const* d_in, const int* in_sizes, int n_in,
                              void* d_out, int out_size)
{
    const float* x       = (const float*)d_in[0];
    const int*   labels  = (const int*)d_in[1];
    const float* centers = (const float*)d_in[2];
    float* out = (float*)d_out;

    cl_fused_kernel<<<CL_NBLOCKS, CL_THREADS>>>(x, labels, centers, out);
}